// round 16
// baseline (speedup 1.0000x reference)
#include <cuda_runtime.h>
#include <cstdint>

// CausalQueue: out[b, 0:C]  = (size == D) ? buffer[head, b, :] : 0
//              out[b, C:2C] = x[b, :]
// x: [B,C] f32, buffer: [D,B,C] f32, size/head int32 device scalars.
// D=128, B=2048, C=512. 16 MB traffic.
//
// R15 (final): measured-best shape from the occ x MLP sweep —
// grid 512 x 256, 4 rows/block, 4 independent front-batched LDG.128 per
// thread (kernel 5.54us, vs 5.92 at occ58/MLP2 and 5.92 at occ16/MLP8).
// Data loads unconditional (head & 127 keeps them in-bounds); size is
// consumed only by a uniform branch at store time, so the not-full path
// never waits on data. x-half warps never touch the scalars. Streaming
// cache hints (__ldcs/__stcs): zero reuse anywhere in the stream.

#define D_CAP  128
#define B_DIM  2048
#define C4     128              // float4 per half-row (C=512)
#define ROW4   256              // float4 per output row
#define RPB    4                // rows per block
#define GRID   (B_DIM / RPB)    // 512

__global__ void __launch_bounds__(256)
causal_queue_kernel(const float4* __restrict__ x,
                    const float4* __restrict__ buffer,
                    const int* __restrict__ size_p,
                    const int* __restrict__ head_p,
                    float4* __restrict__ out)
{
    const int t    = threadIdx.x;        // 0..255 = column in output row
    const int row0 = blockIdx.x * RPB;

    if (t < C4) {
        // ---- past half, column t ----
        const int  size = __ldg(size_p);                 // off the load path
        const int  head = __ldg(head_p) & (D_CAP - 1);   // feeds address, in-bounds

        const float4* src = buffer + (size_t)head * (B_DIM * C4)
                                   + (size_t)row0 * C4 + t;
        float4 v[RPB];
#pragma unroll
        for (int k = 0; k < RPB; k++) v[k] = __ldcs(src + k * C4);  // front-batched

        float4* dst = out + (size_t)row0 * ROW4 + t;
        if (size == D_CAP) {            // uniform across grid: no divergence
#pragma unroll
            for (int k = 0; k < RPB; k++) __stcs(dst + k * ROW4, v[k]);
        } else {
            const float4 z = make_float4(0.f, 0.f, 0.f, 0.f);
#pragma unroll
            for (int k = 0; k < RPB; k++) __stcs(dst + k * ROW4, z);  // no data wait
        }
    } else {
        // ---- x half, column t-128: scalar-free ----
        const float4* src = x + (size_t)row0 * C4 + (t - C4);
        float4 v[RPB];
#pragma unroll
        for (int k = 0; k < RPB; k++) v[k] = __ldcs(src + k * C4);

        float4* dst = out + (size_t)row0 * ROW4 + t;
#pragma unroll
        for (int k = 0; k < RPB; k++) __stcs(dst + k * ROW4, v[k]);
    }
}

extern "C" void kernel_launch(void* const* d_in, const int* in_sizes, int n_in,
                              void* d_out, int out_size)
{
    const float4* x      = (const float4*)d_in[0];   // [B, C] f32
    const float4* buffer = (const float4*)d_in[1];   // [D, B, C] f32
    const int*    size_p = (const int*)d_in[2];      // scalar
    const int*    head_p = (const int*)d_in[3];      // scalar
    float4*       out    = (float4*)d_out;           // [B, 2C] f32

    causal_queue_kernel<<<GRID, 256>>>(x, buffer, size_p, head_p, out);
}

// round 17
// speedup vs baseline: 1.2477x; 1.2477x over previous
#include <cuda_runtime.h>
#include <cstdint>

// CausalQueue: out[b, 0:C]  = (size == D) ? buffer[head, b, :] : 0
//              out[b, C:2C] = x[b, :]
// x: [B,C] f32, buffer: [D,B,C] f32, size/head int32 device scalars.
// D=128, B=2048, C=512. 16 MB logical traffic; reads are L2-resident
// across graph replays (DRAM sees only the ~8 MB output write-back), so
// DEFAULT cache policy is correct — streaming (__ldcs/__stcs) hints
// measurably regressed (kernel 5.54 -> 6.85us) by evicting the
// inter-replay-reused lines.
//
// Final shape (best of 8 structural probes, kernel 5.54us):
//   grid 512 x 256, 4 rows/block, 4 independent front-batched LDG.128
//   per thread (occ~33%, MLP_p1=4 — the occ x MLP sweep optimum).
//   Data loads unconditional (head & 127 keeps them in-bounds for any
//   input); size is consumed only by a uniform branch at store time, so
//   the not-full path never waits on data. x-half warps never touch the
//   scalars. Bench is floored at ~6.6us by the per-replay envelope.

#define D_CAP  128
#define B_DIM  2048
#define C4     128              // float4 per half-row (C=512)
#define ROW4   256              // float4 per output row
#define RPB    4                // rows per block
#define GRID   (B_DIM / RPB)    // 512

__global__ void __launch_bounds__(256)
causal_queue_kernel(const float4* __restrict__ x,
                    const float4* __restrict__ buffer,
                    const int* __restrict__ size_p,
                    const int* __restrict__ head_p,
                    float4* __restrict__ out)
{
    const int t    = threadIdx.x;        // 0..255 = column in output row
    const int row0 = blockIdx.x * RPB;

    if (t < C4) {
        // ---- past half, column t ----
        const int  size = __ldg(size_p);                 // off the load path
        const int  head = __ldg(head_p) & (D_CAP - 1);   // feeds address, in-bounds

        const float4* src = buffer + (size_t)head * (B_DIM * C4)
                                   + (size_t)row0 * C4 + t;
        float4 v[RPB];
#pragma unroll
        for (int k = 0; k < RPB; k++) v[k] = src[k * C4];   // front-batched, MLP=4

        float4* dst = out + (size_t)row0 * ROW4 + t;
        if (size == D_CAP) {            // uniform across grid: no divergence
#pragma unroll
            for (int k = 0; k < RPB; k++) dst[k * ROW4] = v[k];
        } else {
            const float4 z = make_float4(0.f, 0.f, 0.f, 0.f);
#pragma unroll
            for (int k = 0; k < RPB; k++) dst[k * ROW4] = z;   // no data wait
        }
    } else {
        // ---- x half, column t-128: scalar-free ----
        const float4* src = x + (size_t)row0 * C4 + (t - C4);
        float4 v[RPB];
#pragma unroll
        for (int k = 0; k < RPB; k++) v[k] = src[k * C4];

        float4* dst = out + (size_t)row0 * ROW4 + t;
#pragma unroll
        for (int k = 0; k < RPB; k++) dst[k * ROW4] = v[k];
    }
}

extern "C" void kernel_launch(void* const* d_in, const int* in_sizes, int n_in,
                              void* d_out, int out_size)
{
    const float4* x      = (const float4*)d_in[0];   // [B, C] f32
    const float4* buffer = (const float4*)d_in[1];   // [D, B, C] f32
    const int*    size_p = (const int*)d_in[2];      // scalar
    const int*    head_p = (const int*)d_in[3];      // scalar
    float4*       out    = (float4*)d_out;           // [B, 2C] f32

    causal_queue_kernel<<<GRID, 256>>>(x, buffer, size_p, head_p, out);
}